// round 15
// baseline (speedup 1.0000x reference)
#include <cuda_runtime.h>
#include <cstdint>

// Problem constants (fixed shapes from reference):
//   B=4, S=64, F=64, V=16384, E=512, rows = B*S*F = 16384
#define V_DIM  16384
#define V_F4   4096              // float4 per row
#define E_DIM  512
#define NROWS  16384
#define TPB    64                // 2 warps per CTA
#define NWARP  2
#define SLOTS  4                 // independent rows per warp
#define CHF4   128               // float4 per chunk = 512 elems = 2KB
#define GRID   (148 * 13)        // all-resident at 16KB static SMEM/CTA

// SMEM-window slot scan (R14 structure, window moved out of the regfile).
//   Calibration R1-R14: DRAM% is a monotone function of in-flight bytes/SM,
//   and the register file caps a register-held window at ~144KB (R14's
//   2.65 B/cy/warp engine starved at occ 19.7%). Here each warp's 4-slot x
//   2KB window lives in SMEM via cp.async (LDGSTS): 16KB/CTA x 13 CTAs
//   -> ~208KB/SM in flight at regs ~45. Granule 512 elems keeps over-read
//   at 51.6% of x (554MB; +68MB W/out = 622MB total).
//   Per iteration: issue cp.async for all active slots, commit, wait 0,
//   then each lane checks ONLY its own copied bytes (no cross-lane SMEM
//   reads -> no syncs). Hit -> index via FMA position-sum, gather+write
//   (noinline, once per row), refill slot from the atomic queue.
//   x goes through L2 with an evict-first policy (cache_hint) so the W
//   column-gather's sector amplification stays L2-resident; out uses __stcs.

__device__ int g_row_counter;

__global__ void reset_counter_kernel() { g_row_counter = 0; }

__device__ __noinline__ void gather_write(
    int row, int idx, int lane,
    const float* __restrict__ W,
    const float* __restrict__ pos_emb,
    const float* __restrict__ fmap_emb,
    float* __restrict__ out)
{
    const int sr = (row >> 6) & 63;              // row = ((b*64)+s)*64 + f
    const int fm = row & 63;

    const float4* pe = reinterpret_cast<const float4*>(pos_emb  + (size_t)sr * E_DIM);
    const float4* fe = reinterpret_cast<const float4*>(fmap_emb + (size_t)fm * E_DIM);
    float4* o = reinterpret_cast<float4*>(out + (size_t)row * E_DIM);

    #pragma unroll
    for (int j = 0; j < 4; j++) {
        const int q = j * 32 + lane;             // float4 index within row
        const int e = q * 4;
        float4 p = __ldg(&pe[q]);
        float4 g = __ldg(&fe[q]);
        float4 r;
        r.x = __ldg(&W[(size_t)(e + 0) * V_DIM + idx]) + p.x + g.x;
        r.y = __ldg(&W[(size_t)(e + 1) * V_DIM + idx]) + p.y + g.y;
        r.z = __ldg(&W[(size_t)(e + 2) * V_DIM + idx]) + p.z + g.z;
        r.w = __ldg(&W[(size_t)(e + 3) * V_DIM + idx]) + p.w + g.w;
        __stcs(&o[q], r);                        // streaming: protect W in L2
    }
}

__global__ void __launch_bounds__(TPB) combined_embedding_kernel(
    const float* __restrict__ x,
    const float* __restrict__ W,
    const float* __restrict__ pos_emb,
    const float* __restrict__ fmap_emb,
    float* __restrict__ out)
{
    __shared__ float4 buf[NWARP][SLOTS][CHF4];   // 16 KB static

    const int warp = threadIdx.x >> 5;
    const int lane = threadIdx.x & 31;
    const float4* x4 = reinterpret_cast<const float4*>(x);

    // L2 evict-first policy for the x stream (protects W's L2 residency).
    uint64_t pol;
    asm volatile("createpolicy.fractional.L2::evict_first.b64 %0, 1.0;"
                 : "=l"(pol));

    // ---- Claim initial rows ----
    unsigned off4[SLOTS];
    bool act[SLOTS];
    int r0;
    if (lane == 0) r0 = atomicAdd(&g_row_counter, SLOTS);
    r0 = __shfl_sync(0xffffffffu, r0, 0);
    #pragma unroll
    for (int i = 0; i < SLOTS; i++) {
        const int row = r0 + i;
        act[i]  = (row < NROWS);
        off4[i] = (unsigned)row * V_F4;
    }

    while (true) {
        // ---- Issue cp.async for all active slots (up to 8KB in flight) ----
        #pragma unroll
        for (int i = 0; i < SLOTS; i++) {
            if (act[i]) {
                const float4* src = x4 + off4[i] + lane;
                #pragma unroll
                for (int k = 0; k < 4; k++) {
                    unsigned d = (unsigned)__cvta_generic_to_shared(
                        &buf[warp][i][k * 32 + lane]);
                    asm volatile(
                        "cp.async.cg.shared.global.L2::cache_hint "
                        "[%0], [%1], 16, %2;"
                        :: "r"(d), "l"(src + k * 32), "l"(pol) : "memory");
                }
            }
        }
        asm volatile("cp.async.commit_group;" ::: "memory");
        asm volatile("cp.async.wait_group 0;" ::: "memory");

        // ---- Check each slot; each lane reads only its own copies ----
        #pragma unroll
        for (int i = 0; i < SLOTS; i++) {
            if (act[i]) {
                float total = 0.0f, possum = 0.0f;
                #pragma unroll
                for (int k = 0; k < 4; k++) {
                    const float4 v = buf[warp][i][k * 32 + lane];
                    const float t = v.x + v.y + v.z + v.w;
                    const float p = fmaf(v.x, 1.0f,
                                    fmaf(v.y, 2.0f,
                                    fmaf(v.z, 3.0f, v.w * 4.0f)));
                    possum = fmaf(t, (float)((k * 32 + lane) * 4), possum) + p;
                    total += t;
                }

                const unsigned m = __ballot_sync(0xffffffffu, total != 0.0f);
                bool done_row = false;
                int idx = 0, row = 0;
                if (m) {
                    // Hit lane: possum = elem-in-chunk + sub + 1.
                    const int c4   = (int)(off4[i] & (V_F4 - 1));
                    const int cand = c4 * 4 + (int)possum - 1;
                    const int src  = __ffs(m) - 1;
                    idx = __shfl_sync(0xffffffffu, cand, src);
                    row = (int)(off4[i] >> 12);
                    done_row = true;
                } else {
                    off4[i] += CHF4;
                    if ((off4[i] & (V_F4 - 1)) == 0) {
                        // Row exhausted with no hit (impossible for valid
                        // one-hot input) -- bounded fallback.
                        row = (int)(off4[i] >> 12) - 1;
                        idx = 0;
                        done_row = true;
                    }
                }

                if (done_row) {
                    gather_write(row, idx, lane, W, pos_emb, fmap_emb, out);
                    int nr;
                    if (lane == 0) nr = atomicAdd(&g_row_counter, 1);
                    nr = __shfl_sync(0xffffffffu, nr, 0);
                    if (nr < NROWS) off4[i] = (unsigned)nr * V_F4;
                    else            act[i] = false;
                }
            }
        }

        bool any = false;
        #pragma unroll
        for (int i = 0; i < SLOTS; i++) any |= act[i];
        if (!any) return;
    }
}

extern "C" void kernel_launch(void* const* d_in, const int* in_sizes, int n_in,
                              void* d_out, int out_size) {
    const float* x        = (const float*)d_in[0];  // [4,64,64,16384]
    const float* W        = (const float*)d_in[1];  // [512,16384]
    const float* pos_emb  = (const float*)d_in[2];  // [256,512]
    const float* fmap_emb = (const float*)d_in[3];  // [256,512]
    float* out = (float*)d_out;                     // [4,64,64,512]

    (void)in_sizes; (void)n_in; (void)out_size;

    reset_counter_kernel<<<1, 1>>>();
    combined_embedding_kernel<<<GRID, TPB>>>(x, W, pos_emb, fmap_emb, out);
}

// round 16
// speedup vs baseline: 1.1215x; 1.1215x over previous
#include <cuda_runtime.h>

// Problem constants (fixed shapes from reference):
//   B=4, S=64, F=64, V=16384, E=512, rows = B*S*F = 16384
#define V_DIM  16384
#define V_F4   4096              // float4 per row
#define E_DIM  512
#define NROWS  16384
#define TPB    64                // 2 warps per CTA
#define SLOTS  8                 // independent rows scanned per warp
#define CH_F4  64                // float4 per chunk per slot (256 elems, 1KB)
#define GRID   (148 * 11)        // all-resident at ~90 regs

// R14's 8-slot interleaved scan engine (lowest measured traffic: 587MB,
// highest per-warp rate: 2.65 B/cy) with the ONE fix R14 needed: the gather
// epilogue is __noinline__, so its 12 concurrent loads + pointer setup no
// longer inflate the hot loop's register frame (R14: regs=128 -> occ 19.7%;
// R15's noinline epilogue measured 72 regs with comparable machinery).
//   Engine: one warp advances 8 independent rows by 256 elems (1KB granule)
//   per iteration; all 16 float4 loads are issued before any check (8KB
//   window -- the v[] array + per-slot consumption forces ptxas to keep them
//   live), hit index recovered arithmetically, slots refill one-at-a-time
//   from an atomic row queue. Over-read ~50.8% of x (info floor = 50%).
// Phase B: out[row,:] = W[:,idx] + pos_emb[s,:] + fmap_emb[f,:]; W gathered
// column-wise (sector amplification absorbed by L2; x is __ldcs evict-first,
// out is __stcs, so W stays L2-resident).

__device__ int g_row_counter;

__global__ void reset_counter_kernel() { g_row_counter = 0; }

__device__ __noinline__ void gather_write(
    int row, int idx, int lane,
    const float* __restrict__ W,
    const float* __restrict__ pos_emb,
    const float* __restrict__ fmap_emb,
    float* __restrict__ out)
{
    const int sr = (row >> 6) & 63;              // row = ((b*64)+s)*64 + f
    const int fm = row & 63;

    const float4* pe = reinterpret_cast<const float4*>(pos_emb  + (size_t)sr * E_DIM);
    const float4* fe = reinterpret_cast<const float4*>(fmap_emb + (size_t)fm * E_DIM);
    float4* o = reinterpret_cast<float4*>(out + (size_t)row * E_DIM);

    #pragma unroll
    for (int j = 0; j < 4; j++) {
        const int q = j * 32 + lane;             // float4 index within row
        const int e = q * 4;
        float4 p = __ldg(&pe[q]);
        float4 g = __ldg(&fe[q]);
        float4 r;
        r.x = __ldg(&W[(size_t)(e + 0) * V_DIM + idx]) + p.x + g.x;
        r.y = __ldg(&W[(size_t)(e + 1) * V_DIM + idx]) + p.y + g.y;
        r.z = __ldg(&W[(size_t)(e + 2) * V_DIM + idx]) + p.z + g.z;
        r.w = __ldg(&W[(size_t)(e + 3) * V_DIM + idx]) + p.w + g.w;
        __stcs(&o[q], r);                        // streaming: protect W in L2
    }
}

__global__ void __launch_bounds__(TPB) combined_embedding_kernel(
    const float* __restrict__ x,
    const float* __restrict__ W,
    const float* __restrict__ pos_emb,
    const float* __restrict__ fmap_emb,
    float* __restrict__ out)
{
    const int lane = threadIdx.x & 31;
    const float4* x4 = reinterpret_cast<const float4*>(x);

    // Slot state: off4 = row*4096 + c4 (float4 offset into x). Warp-uniform.
    unsigned off4[SLOTS];
    bool act[SLOTS];

    // Grab 8 consecutive rows in one atomic.
    int r0;
    if (lane == 0) r0 = atomicAdd(&g_row_counter, SLOTS);
    r0 = __shfl_sync(0xffffffffu, r0, 0);
    #pragma unroll
    for (int i = 0; i < SLOTS; i++) {
        const int row = r0 + i;
        act[i]  = (row < NROWS);
        off4[i] = (unsigned)row * V_F4;
    }

    while (true) {
        // ---- Issue ALL loads first: 16 x float4 = 8KB warp window ----
        float4 va[SLOTS], vb[SLOTS];
        #pragma unroll
        for (int i = 0; i < SLOTS; i++) {
            if (act[i]) {
                va[i] = __ldcs(&x4[off4[i] + lane]);
                vb[i] = __ldcs(&x4[off4[i] + 32 + lane]);
            }
        }

        // ---- Then all checks (each consumes only its own slot's data) ----
        #pragma unroll
        for (int i = 0; i < SLOTS; i++) {
            if (act[i]) {
                const float Ta = va[i].x + va[i].y + va[i].z + va[i].w;
                const float Tb = vb[i].x + vb[i].y + vb[i].z + vb[i].w;
                // S = sum((k+1)*v) over both float4, immediate weights.
                float S = 0.0f;
                S = fmaf(va[i].x, 1.0f, S);
                S = fmaf(va[i].y, 2.0f, S);
                S = fmaf(va[i].z, 3.0f, S);
                S = fmaf(va[i].w, 4.0f, S);
                S = fmaf(vb[i].x, 1.0f, S);
                S = fmaf(vb[i].y, 2.0f, S);
                S = fmaf(vb[i].z, 3.0f, S);
                S = fmaf(vb[i].w, 4.0f, S);

                const unsigned m = __ballot_sync(0xffffffffu, (Ta + Tb) != 0.0f);
                if (m) {
                    // Hit lane: rel-in-chunk = (S-1) + 4*lane + 128*(hit in vb).
                    const int c4   = (int)(off4[i] & (V_F4 - 1));
                    const int cand = c4 * 4 + lane * 4 + (int)S - 1
                                   + (Tb != 0.0f ? 128 : 0);
                    const int src  = __ffs(m) - 1;
                    const int idx  = __shfl_sync(0xffffffffu, cand, src);
                    const int row  = (int)(off4[i] >> 12);   // off4 / 4096

                    if (row < NROWS)
                        gather_write(row, idx, lane, W, pos_emb, fmap_emb, out);

                    // Refill slot from the queue.
                    int nr;
                    if (lane == 0) nr = atomicAdd(&g_row_counter, 1);
                    nr = __shfl_sync(0xffffffffu, nr, 0);
                    if (nr < NROWS) off4[i] = (unsigned)nr * V_F4;
                    else            act[i] = false;
                } else {
                    off4[i] += CH_F4;            // advance this row by 1KB
                }
            }
        }

        bool any = false;
        #pragma unroll
        for (int i = 0; i < SLOTS; i++) any |= act[i];
        if (!any) return;
    }
}

extern "C" void kernel_launch(void* const* d_in, const int* in_sizes, int n_in,
                              void* d_out, int out_size) {
    const float* x        = (const float*)d_in[0];  // [4,64,64,16384]
    const float* W        = (const float*)d_in[1];  // [512,16384]
    const float* pos_emb  = (const float*)d_in[2];  // [256,512]
    const float* fmap_emb = (const float*)d_in[3];  // [256,512]
    float* out = (float*)d_out;                     // [4,64,64,512]

    (void)in_sizes; (void)n_in; (void)out_size;

    reset_counter_kernel<<<1, 1>>>();
    combined_embedding_kernel<<<GRID, TPB>>>(x, W, pos_emb, fmap_emb, out);
}

// round 17
// speedup vs baseline: 1.1545x; 1.0294x over previous
#include <cuda_runtime.h>

// Problem constants (fixed shapes from reference):
//   B=4, S=64, F=64, V=16384, E=512, rows = B*S*F = 16384
#define V_DIM 16384
#define E_DIM 512
#define NROWS 16384
#define TPB   64                 // 2 warps per CTA
#define WPB   (TPB / 32)
#define BURST 8                  // float4 loads per lane per burst
#define BELEM (BURST * 32 * 4)   // 1024 elements per burst
#define NBURST (V_DIM / BELEM)   // 16 bursts per row

// R9 (best kernel, 102.8us) with ONE change: x is read with plain cached
// loads instead of __ldcs.
//   Isolation experiment: every kernel R2-R16 used __ldcs for the x stream
//   and equilibrated at 5.9-6.3 TB/s across wildly different structures;
//   R1 -- the only kernel on default-policy loads -- measured 7.04 TB/s
//   (88.8% DRAM). Hypothesis: the L2 evict-first policy itself caps
//   streaming read BW, and the W-protection it buys has never been visible
//   in measured traffic. Risk: x may now thrash W out of L2 (bounded:
//   W unique = 33.5MB; worst-case refetch ~ +100MB).
// Engine (unchanged from R9): warp-per-row, bursts of 8 independent float4
// per lane (4KB/warp in flight), 0/1-sum + ballot check per burst, exit at
// 1024-element granularity (53.1% of x read). Phase B: W column gather +
// pos/fmap add, __stcs output.
__global__ void __launch_bounds__(TPB) combined_embedding_kernel(
    const float* __restrict__ x,
    const float* __restrict__ W,
    const float* __restrict__ pos_emb,
    const float* __restrict__ fmap_emb,
    float* __restrict__ out)
{
    const int warp = threadIdx.x >> 5;
    const int lane = threadIdx.x & 31;
    const int row  = blockIdx.x * WPB + warp;

    const float4* xr = reinterpret_cast<const float4*>(x + (size_t)row * V_DIM);

    int idx = -1;

    #pragma unroll 1
    for (int b = 0; b < NBURST; b++) {
        // 8 independent loads back-to-back: 4KB in flight for this warp.
        // Plain cached loads (the experiment variable -- R9 used __ldcs).
        float4 v0 = xr[b * 256 + 0 * 32 + lane];
        float4 v1 = xr[b * 256 + 1 * 32 + lane];
        float4 v2 = xr[b * 256 + 2 * 32 + lane];
        float4 v3 = xr[b * 256 + 3 * 32 + lane];
        float4 v4 = xr[b * 256 + 4 * 32 + lane];
        float4 v5 = xr[b * 256 + 5 * 32 + lane];
        float4 v6 = xr[b * 256 + 6 * 32 + lane];
        float4 v7 = xr[b * 256 + 7 * 32 + lane];

        // 0/1 data: sum != 0 <=> this lane saw the one-hot element.
        float s = v0.x + v0.y + v0.z + v0.w
                + v1.x + v1.y + v1.z + v1.w
                + v2.x + v2.y + v2.z + v2.w
                + v3.x + v3.y + v3.z + v3.w
                + v4.x + v4.y + v4.z + v4.w
                + v5.x + v5.y + v5.z + v5.w
                + v6.x + v6.y + v6.z + v6.w
                + v7.x + v7.y + v7.z + v7.w;

        const unsigned m = __ballot_sync(0xffffffffu, s != 0.0f);
        if (m) {
            // Rare path (once per row): locate the element within the burst.
            int f = -1;
            const float4 vv[8] = {v0, v1, v2, v3, v4, v5, v6, v7};
            #pragma unroll
            for (int j = 0; j < 8; j++) {
                const int base = (b * 256 + j * 32 + lane) * 4;
                if (vv[j].x != 0.0f) f = base + 0;
                if (vv[j].y != 0.0f) f = base + 1;
                if (vv[j].z != 0.0f) f = base + 2;
                if (vv[j].w != 0.0f) f = base + 3;
            }
            const int src = __ffs(m) - 1;
            idx = __shfl_sync(0xffffffffu, f, src);
            break;
        }
    }
    if (idx < 0) idx = 0;

    // ---- Phase B: gather + add, warp-wide (unchanged from R9) ----
    {
        const int s  = (row >> 6) & 63;              // row = ((b*64)+s)*64 + f
        const int fm = row & 63;

        const float4* pe = reinterpret_cast<const float4*>(pos_emb  + (size_t)s  * E_DIM);
        const float4* fe = reinterpret_cast<const float4*>(fmap_emb + (size_t)fm * E_DIM);
        float4* o = reinterpret_cast<float4*>(out + (size_t)row * E_DIM);

        // E=512 -> 128 float4; 32 lanes x 4. W gather: column idx, stride V.
        #pragma unroll
        for (int j = 0; j < 4; j++) {
            const int q = j * 32 + lane;             // float4 index within row
            const int e = q * 4;
            float4 p = __ldg(&pe[q]);
            float4 g = __ldg(&fe[q]);
            float4 r;
            r.x = __ldg(&W[(size_t)(e + 0) * V_DIM + idx]) + p.x + g.x;
            r.y = __ldg(&W[(size_t)(e + 1) * V_DIM + idx]) + p.y + g.y;
            r.z = __ldg(&W[(size_t)(e + 2) * V_DIM + idx]) + p.z + g.z;
            r.w = __ldg(&W[(size_t)(e + 3) * V_DIM + idx]) + p.w + g.w;
            __stcs(&o[q], r);
        }
    }
}

extern "C" void kernel_launch(void* const* d_in, const int* in_sizes, int n_in,
                              void* d_out, int out_size) {
    const float* x        = (const float*)d_in[0];  // [4,64,64,16384]
    const float* W        = (const float*)d_in[1];  // [512,16384]
    const float* pos_emb  = (const float*)d_in[2];  // [256,512]
    const float* fmap_emb = (const float*)d_in[3];  // [256,512]
    float* out = (float*)d_out;                     // [4,64,64,512]

    (void)in_sizes; (void)n_in; (void)out_size;

    combined_embedding_kernel<<<NROWS / WPB, TPB>>>(x, W, pos_emb, fmap_emb, out);
}